// round 1
// baseline (speedup 1.0000x reference)
#include <cuda_runtime.h>
#include <cuda_bf16.h>
#include <math.h>

// Problem dims
#define BB 16
#define SS 128
#define KK 49
#define NT 5
#define EE 512
#define HH 512
#define VOCAB 30000
#define ROWS (BB*SS)          // 2048

// ---------------- device scratch (no allocation allowed) ----------------
__device__ float g_linV [BB*KK*KK];     // V @ W_ZV.T + b_ZV            [B,K,49]
__device__ float g_linH [ROWS*KK];      // h @ W_Zh.T + b_Zh            [B*S,49]
__device__ float g_linQT[BB*NT*NT];     // T @ W_QT.T + b_QT            [B,5,5]
__device__ float g_linQh[ROWS*NT];      // h @ W_Qh.T + b_Qh            [B*S,5]
__device__ float g_z [ROWS*HH];         // z_t
__device__ float g_q [ROWS*EE];         // q_t
__device__ float g_r [ROWS*EE];         // r_t
__device__ float g_s [ROWS*EE];         // s_t
__device__ float g_c [ROWS*EE];         // c_t
__device__ float g_gama[SS];            // gate per s

// ---------------- K0: tall-skinny linear  Y[row,j] = b[j] + X[row,:].W[j,:] ----------------
// one block per row (row length 512), warp-per-output with shuffle reduce
__global__ void small_lin_kernel(const float* __restrict__ X,
                                 const float* __restrict__ W,
                                 const float* __restrict__ bias,
                                 float* __restrict__ Y, int J)
{
    __shared__ float xs[512];
    int row = blockIdx.x;
    const float* x = X + (size_t)row * 512;
    for (int i = threadIdx.x; i < 512; i += blockDim.x) xs[i] = x[i];
    __syncthreads();
    int warp = threadIdx.x >> 5, lane = threadIdx.x & 31;
    int nw = blockDim.x >> 5;
    for (int j = warp; j < J; j += nw) {
        const float* w = W + (size_t)j * 512;
        float p = 0.f;
        #pragma unroll 4
        for (int i = lane; i < 512; i += 32) p += xs[i] * w[i];
        #pragma unroll
        for (int o = 16; o; o >>= 1) p += __shfl_xor_sync(0xffffffffu, p, o);
        if (lane == 0) Y[(size_t)row * J + j] = p + bias[j];
    }
}

// ---------------- K1: visual attention + z_t, one block per (b,s) ----------------
__global__ void visual_kernel(const float* __restrict__ V,
                              const float* __restrict__ linV,
                              const float* __restrict__ linH,
                              const float* __restrict__ W_az,
                              const float* __restrict__ b_az,
                              float* __restrict__ z)
{
    int bx = blockIdx.x;
    int b = bx >> 7, s = bx & 127;
    int tid = threadIdx.x;
    int warp = tid >> 5, lane = tid & 31;

    __shared__ float lh[KK], waz[KK], vis[KK], red[1];

    if (tid < KK) {
        lh[tid]  = linH[((size_t)(b * SS + s)) * KK + tid];
        waz[tid] = W_az[tid];
    }
    __syncthreads();

    const float* lv = linV + (size_t)b * KK * KK;
    float baz = b_az[0];
    for (int k = warp; k < KK; k += 8) {
        const float* lvk = lv + (size_t)k * KK;
        float p = 0.f;
        for (int j = lane; j < KK; j += 32) p += tanhf(lvk[j] + lh[j]) * waz[j];
        #pragma unroll
        for (int o = 16; o; o >>= 1) p += __shfl_xor_sync(0xffffffffu, p, o);
        if (lane == 0) vis[k] = p + baz;
    }
    __syncthreads();

    // softmax over 49 (warp 0)
    if (warp == 0) {
        float m = -1e30f;
        for (int k = lane; k < KK; k += 32) m = fmaxf(m, vis[k]);
        #pragma unroll
        for (int o = 16; o; o >>= 1) m = fmaxf(m, __shfl_xor_sync(0xffffffffu, m, o));
        float ssum = 0.f;
        for (int k = lane; k < KK; k += 32) { float e = expf(vis[k] - m); vis[k] = e; ssum += e; }
        #pragma unroll
        for (int o = 16; o; o >>= 1) ssum += __shfl_xor_sync(0xffffffffu, ssum, o);
        if (lane == 0) red[0] = 1.0f / ssum;
    }
    __syncthreads();
    float inv = red[0];

    const float* Vb = V + (size_t)b * KK * HH;
    float* zrow = z + ((size_t)(b * SS + s)) * HH;
    for (int h = tid; h < HH; h += blockDim.x) {
        float acc = 0.f;
        #pragma unroll 7
        for (int k = 0; k < KK; k++) acc += vis[k] * Vb[(size_t)k * HH + h];
        zrow[h] = acc * inv;
    }
}

// ---------------- K2: topic attention + q_t, one block per (b,s) ----------------
__global__ void topic_kernel(const float* __restrict__ T,
                             const float* __restrict__ linQT,
                             const float* __restrict__ linQh,
                             const float* __restrict__ W_bq,
                             const float* __restrict__ b_bq,
                             float* __restrict__ q)
{
    int bx = blockIdx.x;
    int b = bx >> 7, s = bx & 127;
    int tid = threadIdx.x;

    __shared__ float lqh[NT], tp[NT], betas[NT];

    if (tid < NT) lqh[tid] = linQh[((size_t)(b * SS + s)) * NT + tid];
    __syncthreads();
    if (tid < NT) {
        const float* lq = linQT + (size_t)b * NT * NT + (size_t)tid * NT;
        float p = b_bq[0];
        #pragma unroll
        for (int j = 0; j < NT; j++) p += tanhf(lq[j] + lqh[j]) * W_bq[j];
        tp[tid] = p;
    }
    __syncthreads();
    if (tid == 0) {
        float m = tp[0];
        #pragma unroll
        for (int t = 1; t < NT; t++) m = fmaxf(m, tp[t]);
        float ssum = 0.f;
        #pragma unroll
        for (int t = 0; t < NT; t++) { betas[t] = expf(tp[t] - m); ssum += betas[t]; }
        float inv = 1.0f / ssum;
        #pragma unroll
        for (int t = 0; t < NT; t++) betas[t] *= inv;
    }
    __syncthreads();

    const float* Tb = T + (size_t)b * NT * EE;
    float* qrow = q + ((size_t)(b * SS + s)) * EE;
    for (int h = tid; h < EE; h += blockDim.x) {
        float acc = 0.f;
        #pragma unroll
        for (int t = 0; t < NT; t++) acc += betas[t] * Tb[(size_t)t * EE + h];
        qrow[h] = acc;
    }
}

// ---------------- K3: mid GEMM  C = tanh(A1 W1^T [+ A2 W2^T] + b1 [+ b2]) ----------------
// M=2048, N=512, K=512; BM=BN=64, BK=16, 256 threads, 4x4 microtile
template<bool DUAL>
__global__ __launch_bounds__(256)
void mid_gemm_tanh(const float* __restrict__ A1, const float* __restrict__ W1,
                   const float* __restrict__ b1,
                   const float* __restrict__ A2, const float* __restrict__ W2,
                   const float* __restrict__ b2,
                   float* __restrict__ C)
{
    __shared__ float As[16][64];
    __shared__ float Ws[16][64];
    int tid = threadIdx.x;
    int tx = tid & 15, ty = tid >> 4;
    int m0 = blockIdx.y * 64, n0 = blockIdx.x * 64;
    int lr = tid >> 2;             // 0..63
    int lc = (tid & 3) * 4;        // 0,4,8,12

    float acc[4][4] = {};
    int passes = DUAL ? 2 : 1;
    for (int pass = 0; pass < passes; pass++) {
        const float* A = pass ? A2 : A1;
        const float* W = pass ? W2 : W1;
        const float* Ap = A + (size_t)(m0 + lr) * 512 + lc;
        const float* Wp = W + (size_t)(n0 + lr) * 512 + lc;
        for (int k0 = 0; k0 < 512; k0 += 16) {
            float4 av = *(const float4*)(Ap + k0);
            float4 wv = *(const float4*)(Wp + k0);
            As[lc + 0][lr] = av.x; As[lc + 1][lr] = av.y;
            As[lc + 2][lr] = av.z; As[lc + 3][lr] = av.w;
            Ws[lc + 0][lr] = wv.x; Ws[lc + 1][lr] = wv.y;
            Ws[lc + 2][lr] = wv.z; Ws[lc + 3][lr] = wv.w;
            __syncthreads();
            #pragma unroll
            for (int k = 0; k < 16; k++) {
                float a[4], w[4];
                *(float4*)a = *(const float4*)&As[k][ty * 4];
                *(float4*)w = *(const float4*)&Ws[k][tx * 4];
                #pragma unroll
                for (int i = 0; i < 4; i++)
                    #pragma unroll
                    for (int j = 0; j < 4; j++)
                        acc[i][j] += a[i] * w[j];
            }
            __syncthreads();
        }
    }
    #pragma unroll
    for (int j = 0; j < 4; j++) {
        int n = n0 + tx * 4 + j;
        float bj = b1[n];
        if (DUAL) bj += b2[n];
        #pragma unroll
        for (int i = 0; i < 4; i++) {
            int m = m0 + ty * 4 + i;
            C[(size_t)m * 512 + n] = tanhf(acc[i][j] + bj);
        }
    }
}

// ---------------- K4: sentinel scores + gate, one warp per s (batch 0 only) ----------------
__global__ void sentinel_kernel(const void* __restrict__ epoch_p,
                                const float* __restrict__ sT,
                                const float* __restrict__ rT,
                                const float* __restrict__ qh0,   // g_linQh rows of b=0
                                const float* __restrict__ W_Ss, const float* __restrict__ b_Ss,
                                const float* __restrict__ W_Sr, const float* __restrict__ b_Sr,
                                const float* __restrict__ W_bq, const float* __restrict__ b_bq,
                                float* __restrict__ gama)
{
    int s = blockIdx.x;
    int lane = threadIdx.x;
    // epoch may arrive as int32/int64 or float32; decode by bit pattern
    int iv = *(const int*)epoch_p;
    int epoch = (iv >= 0 && iv < 1000000) ? iv : (int)(*(const float*)epoch_p);
    if (epoch <= 20) { if (lane == 0) gama[s] = 1.0f; return; }

    const float* srow = sT + (size_t)s * EE;   // batch 0
    const float* rrow = rT + (size_t)s * EE;
    float ss = 0.f, sr = 0.f;
    #pragma unroll
    for (int j = 0; j < NT; j++) {
        const float* w1 = W_Ss + (size_t)j * EE;
        const float* w2 = W_Sr + (size_t)j * EE;
        float p1 = 0.f, p2 = 0.f;
        for (int i = lane; i < EE; i += 32) { p1 += srow[i] * w1[i]; p2 += rrow[i] * w2[i]; }
        #pragma unroll
        for (int o = 16; o; o >>= 1) {
            p1 += __shfl_xor_sync(0xffffffffu, p1, o);
            p2 += __shfl_xor_sync(0xffffffffu, p2, o);
        }
        float qh = qh0[(size_t)s * NT + j];
        ss += tanhf(p1 + b_Ss[j] + qh) * W_bq[j];
        sr += tanhf(p2 + b_Sr[j] + qh) * W_bq[j];
    }
    if (lane == 0) {
        float d = ss - sr;                 // b_bq cancels in the difference
        gama[s] = 1.0f / (1.0f + expf(-d));
    }
}

// ---------------- K5: c_t = g*s_t + (1-g)*r_t ----------------
__global__ void mix_kernel(const float* __restrict__ sT, const float* __restrict__ rT,
                           const float* __restrict__ gama, float* __restrict__ c)
{
    int idx = blockIdx.x * blockDim.x + threadIdx.x;
    if (idx >= ROWS * EE) return;
    int srow = (idx >> 9) & 127;           // s index (E=512)
    float g = gama[srow];
    c[idx] = g * sT[idx] + (1.0f - g) * rT[idx];
}

// ---------------- K6: vocab GEMM  out = c_t @ W_mlp^T + b_mlp ----------------
// M=2048, N=30000, K=512; BM=BN=128, BK=8, 256 threads, 8x8 microtile
__global__ __launch_bounds__(256)
void vocab_gemm(const float* __restrict__ A,      // [2048,512]
                const float* __restrict__ W,      // [30000,512]
                const float* __restrict__ bias,   // [30000]
                float* __restrict__ C)            // [2048,30000]
{
    __shared__ float As[8][128];
    __shared__ float Ws[8][128];
    int tid = threadIdx.x;
    int tx = tid & 15, ty = tid >> 4;
    int m0 = blockIdx.y * 128, n0 = blockIdx.x * 128;

    int lr = tid >> 1;            // 0..127
    int lc = (tid & 1) * 4;       // 0 or 4
    const float* Ap = A + (size_t)(m0 + lr) * 512 + lc;
    bool wvalid = (n0 + lr) < VOCAB;
    const float* Wp = W + (size_t)(n0 + lr) * 512 + lc;

    float acc[8][8] = {};
    for (int k0 = 0; k0 < 512; k0 += 8) {
        float4 av = *(const float4*)(Ap + k0);
        float4 wv = wvalid ? *(const float4*)(Wp + k0) : make_float4(0.f, 0.f, 0.f, 0.f);
        As[lc + 0][lr] = av.x; As[lc + 1][lr] = av.y;
        As[lc + 2][lr] = av.z; As[lc + 3][lr] = av.w;
        Ws[lc + 0][lr] = wv.x; Ws[lc + 1][lr] = wv.y;
        Ws[lc + 2][lr] = wv.z; Ws[lc + 3][lr] = wv.w;
        __syncthreads();
        #pragma unroll
        for (int k = 0; k < 8; k++) {
            float a[8], w[8];
            *(float4*)(a + 0) = *(const float4*)&As[k][ty * 8 + 0];
            *(float4*)(a + 4) = *(const float4*)&As[k][ty * 8 + 4];
            *(float4*)(w + 0) = *(const float4*)&Ws[k][tx * 8 + 0];
            *(float4*)(w + 4) = *(const float4*)&Ws[k][tx * 8 + 4];
            #pragma unroll
            for (int i = 0; i < 8; i++)
                #pragma unroll
                for (int j = 0; j < 8; j++)
                    acc[i][j] += a[i] * w[j];
        }
        __syncthreads();
    }
    // epilogue: float4 stores; 30000 % 8 == 0 so validity is exact per float4 group
    #pragma unroll
    for (int i = 0; i < 8; i++) {
        int m = m0 + ty * 8 + i;
        float* crow = C + (size_t)m * VOCAB + n0 + tx * 8;
        #pragma unroll
        for (int j4 = 0; j4 < 8; j4 += 4) {
            int n = n0 + tx * 8 + j4;
            if (n + 3 < VOCAB) {
                float4 v;
                v.x = acc[i][j4 + 0] + bias[n + 0];
                v.y = acc[i][j4 + 1] + bias[n + 1];
                v.z = acc[i][j4 + 2] + bias[n + 2];
                v.w = acc[i][j4 + 3] + bias[n + 3];
                *(float4*)(crow + j4) = v;
            }
        }
    }
}

// ---------------- launch ----------------
extern "C" void kernel_launch(void* const* d_in, const int* in_sizes, int n_in,
                              void* d_out, int out_size)
{
    const void*  epoch = d_in[0];
    const float* h_t  = (const float*)d_in[1];
    const float* V    = (const float*)d_in[2];
    const float* T    = (const float*)d_in[3];
    const float* W_ZV = (const float*)d_in[4];   const float* b_ZV = (const float*)d_in[5];
    const float* W_Zh = (const float*)d_in[6];   const float* b_Zh = (const float*)d_in[7];
    const float* W_az = (const float*)d_in[8];   const float* b_az = (const float*)d_in[9];
    const float* W_QT = (const float*)d_in[10];  const float* b_QT = (const float*)d_in[11];
    const float* W_Qh = (const float*)d_in[12];  const float* b_Qh = (const float*)d_in[13];
    const float* W_bq = (const float*)d_in[14];  const float* b_bq = (const float*)d_in[15];
    const float* W_sq = (const float*)d_in[16];  const float* b_sq = (const float*)d_in[17];
    const float* W_sh = (const float*)d_in[18];  const float* b_sh = (const float*)d_in[19];
    const float* W_Ss = (const float*)d_in[20];  const float* b_Ss = (const float*)d_in[21];
    const float* W_Sr = (const float*)d_in[22];  const float* b_Sr = (const float*)d_in[23];
    const float* W_sz = (const float*)d_in[24];  const float* b_sz = (const float*)d_in[25];
    const float* W_mlp= (const float*)d_in[26];  const float* b_mlp= (const float*)d_in[27];
    float* out = (float*)d_out;

    float *linV, *linH, *linQT, *linQh, *z, *q, *r, *s, *c, *gama;
    cudaGetSymbolAddress((void**)&linV,  g_linV);
    cudaGetSymbolAddress((void**)&linH,  g_linH);
    cudaGetSymbolAddress((void**)&linQT, g_linQT);
    cudaGetSymbolAddress((void**)&linQh, g_linQh);
    cudaGetSymbolAddress((void**)&z,     g_z);
    cudaGetSymbolAddress((void**)&q,     g_q);
    cudaGetSymbolAddress((void**)&r,     g_r);
    cudaGetSymbolAddress((void**)&s,     g_s);
    cudaGetSymbolAddress((void**)&c,     g_c);
    cudaGetSymbolAddress((void**)&gama,  g_gama);

    // K0: small linears
    small_lin_kernel<<<BB*KK, 128>>>(V,   W_ZV, b_ZV, linV,  KK);
    small_lin_kernel<<<ROWS,  128>>>(h_t, W_Zh, b_Zh, linH,  KK);
    small_lin_kernel<<<BB*NT, 128>>>(T,   W_QT, b_QT, linQT, NT);
    small_lin_kernel<<<ROWS,  128>>>(h_t, W_Qh, b_Qh, linQh, NT);

    // K1/K2: attentions
    visual_kernel<<<ROWS, 256>>>(V, linV, linH, W_az, b_az, z);
    topic_kernel <<<ROWS, 256>>>(T, linQT, linQh, W_bq, b_bq, q);

    // K3: mid GEMMs
    mid_gemm_tanh<true ><<<dim3(512/64, ROWS/64), 256>>>(q, W_sq, b_sq, h_t, W_sh, b_sh, s);
    mid_gemm_tanh<false><<<dim3(512/64, ROWS/64), 256>>>(z, W_sz, b_sz, nullptr, nullptr, nullptr, r);

    // K4: sentinel gate (batch 0, diagonal)
    sentinel_kernel<<<SS, 32>>>(epoch, s, r, linQh, W_Ss, b_Ss, W_Sr, b_Sr, W_bq, b_bq, gama);

    // K5: mix
    mix_kernel<<<(ROWS*EE + 255)/256, 256>>>(s, r, gama, c);

    // K6: vocab projection
    vocab_gemm<<<dim3((VOCAB + 127)/128, ROWS/128), 256>>>(c, W_mlp, b_mlp, out);
}

// round 2
// speedup vs baseline: 2.2665x; 2.2665x over previous
#include <cuda_runtime.h>
#include <cuda_bf16.h>
#include <math.h>

// Problem dims
#define BB 16
#define SS 128
#define KK 49
#define NT 5
#define EE 512
#define HH 512
#define VOCAB 30000
#define ROWS (BB*SS)          // 2048

// ---------------- device scratch (no allocation allowed) ----------------
__device__ float g_linV [BB*KK*KK];
__device__ float g_linH [ROWS*KK];
__device__ float g_linQT[BB*NT*NT];
__device__ float g_linQh[ROWS*NT];
__device__ float g_z [ROWS*HH];
__device__ float g_q [ROWS*EE];
__device__ float g_r [ROWS*EE];
__device__ float g_s [ROWS*EE];
__device__ float g_c [ROWS*EE];
__device__ float g_gama[SS];

// ---------------- K0: tall-skinny linear ----------------
__global__ void small_lin_kernel(const float* __restrict__ X,
                                 const float* __restrict__ W,
                                 const float* __restrict__ bias,
                                 float* __restrict__ Y, int J)
{
    __shared__ float xs[512];
    int row = blockIdx.x;
    const float* x = X + (size_t)row * 512;
    for (int i = threadIdx.x; i < 512; i += blockDim.x) xs[i] = x[i];
    __syncthreads();
    int warp = threadIdx.x >> 5, lane = threadIdx.x & 31;
    int nw = blockDim.x >> 5;
    for (int j = warp; j < J; j += nw) {
        const float* w = W + (size_t)j * 512;
        float p = 0.f;
        #pragma unroll 4
        for (int i = lane; i < 512; i += 32) p += xs[i] * w[i];
        #pragma unroll
        for (int o = 16; o; o >>= 1) p += __shfl_xor_sync(0xffffffffu, p, o);
        if (lane == 0) Y[(size_t)row * J + j] = p + bias[j];
    }
}

// ---------------- K1: visual attention + z_t ----------------
__global__ void visual_kernel(const float* __restrict__ V,
                              const float* __restrict__ linV,
                              const float* __restrict__ linH,
                              const float* __restrict__ W_az,
                              const float* __restrict__ b_az,
                              float* __restrict__ z)
{
    int bx = blockIdx.x;
    int b = bx >> 7, s = bx & 127;
    int tid = threadIdx.x;
    int warp = tid >> 5, lane = tid & 31;

    __shared__ float lh[KK], waz[KK], vis[KK], red[1];

    if (tid < KK) {
        lh[tid]  = linH[((size_t)(b * SS + s)) * KK + tid];
        waz[tid] = W_az[tid];
    }
    __syncthreads();

    const float* lv = linV + (size_t)b * KK * KK;
    float baz = b_az[0];
    for (int k = warp; k < KK; k += 8) {
        const float* lvk = lv + (size_t)k * KK;
        float p = 0.f;
        for (int j = lane; j < KK; j += 32) p += tanhf(lvk[j] + lh[j]) * waz[j];
        #pragma unroll
        for (int o = 16; o; o >>= 1) p += __shfl_xor_sync(0xffffffffu, p, o);
        if (lane == 0) vis[k] = p + baz;
    }
    __syncthreads();

    if (warp == 0) {
        float m = -1e30f;
        for (int k = lane; k < KK; k += 32) m = fmaxf(m, vis[k]);
        #pragma unroll
        for (int o = 16; o; o >>= 1) m = fmaxf(m, __shfl_xor_sync(0xffffffffu, m, o));
        float ssum = 0.f;
        for (int k = lane; k < KK; k += 32) { float e = expf(vis[k] - m); vis[k] = e; ssum += e; }
        #pragma unroll
        for (int o = 16; o; o >>= 1) ssum += __shfl_xor_sync(0xffffffffu, ssum, o);
        if (lane == 0) red[0] = 1.0f / ssum;
    }
    __syncthreads();
    float inv = red[0];

    const float* Vb = V + (size_t)b * KK * HH;
    float* zrow = z + ((size_t)(b * SS + s)) * HH;
    for (int h = tid; h < HH; h += blockDim.x) {
        float acc = 0.f;
        #pragma unroll 7
        for (int k = 0; k < KK; k++) acc += vis[k] * Vb[(size_t)k * HH + h];
        zrow[h] = acc * inv;
    }
}

// ---------------- K2: topic attention + q_t ----------------
__global__ void topic_kernel(const float* __restrict__ T,
                             const float* __restrict__ linQT,
                             const float* __restrict__ linQh,
                             const float* __restrict__ W_bq,
                             const float* __restrict__ b_bq,
                             float* __restrict__ q)
{
    int bx = blockIdx.x;
    int b = bx >> 7, s = bx & 127;
    int tid = threadIdx.x;

    __shared__ float lqh[NT], tp[NT], betas[NT];

    if (tid < NT) lqh[tid] = linQh[((size_t)(b * SS + s)) * NT + tid];
    __syncthreads();
    if (tid < NT) {
        const float* lq = linQT + (size_t)b * NT * NT + (size_t)tid * NT;
        float p = b_bq[0];
        #pragma unroll
        for (int j = 0; j < NT; j++) p += tanhf(lq[j] + lqh[j]) * W_bq[j];
        tp[tid] = p;
    }
    __syncthreads();
    if (tid == 0) {
        float m = tp[0];
        #pragma unroll
        for (int t = 1; t < NT; t++) m = fmaxf(m, tp[t]);
        float ssum = 0.f;
        #pragma unroll
        for (int t = 0; t < NT; t++) { betas[t] = expf(tp[t] - m); ssum += betas[t]; }
        float inv = 1.0f / ssum;
        #pragma unroll
        for (int t = 0; t < NT; t++) betas[t] *= inv;
    }
    __syncthreads();

    const float* Tb = T + (size_t)b * NT * EE;
    float* qrow = q + ((size_t)(b * SS + s)) * EE;
    for (int h = tid; h < EE; h += blockDim.x) {
        float acc = 0.f;
        #pragma unroll
        for (int t = 0; t < NT; t++) acc += betas[t] * Tb[(size_t)t * EE + h];
        qrow[h] = acc;
    }
}

// ---------------- K3: mid GEMM (FFMA), tanh epilogue ----------------
template<bool DUAL>
__global__ __launch_bounds__(256)
void mid_gemm_tanh(const float* __restrict__ A1, const float* __restrict__ W1,
                   const float* __restrict__ b1,
                   const float* __restrict__ A2, const float* __restrict__ W2,
                   const float* __restrict__ b2,
                   float* __restrict__ C)
{
    __shared__ float As[16][64];
    __shared__ float Ws[16][64];
    int tid = threadIdx.x;
    int tx = tid & 15, ty = tid >> 4;
    int m0 = blockIdx.y * 64, n0 = blockIdx.x * 64;
    int lr = tid >> 2;
    int lc = (tid & 3) * 4;

    float acc[4][4] = {};
    int passes = DUAL ? 2 : 1;
    for (int pass = 0; pass < passes; pass++) {
        const float* A = pass ? A2 : A1;
        const float* W = pass ? W2 : W1;
        const float* Ap = A + (size_t)(m0 + lr) * 512 + lc;
        const float* Wp = W + (size_t)(n0 + lr) * 512 + lc;
        for (int k0 = 0; k0 < 512; k0 += 16) {
            float4 av = *(const float4*)(Ap + k0);
            float4 wv = *(const float4*)(Wp + k0);
            As[lc + 0][lr] = av.x; As[lc + 1][lr] = av.y;
            As[lc + 2][lr] = av.z; As[lc + 3][lr] = av.w;
            Ws[lc + 0][lr] = wv.x; Ws[lc + 1][lr] = wv.y;
            Ws[lc + 2][lr] = wv.z; Ws[lc + 3][lr] = wv.w;
            __syncthreads();
            #pragma unroll
            for (int k = 0; k < 16; k++) {
                float a[4], w[4];
                *(float4*)a = *(const float4*)&As[k][ty * 4];
                *(float4*)w = *(const float4*)&Ws[k][tx * 4];
                #pragma unroll
                for (int i = 0; i < 4; i++)
                    #pragma unroll
                    for (int j = 0; j < 4; j++)
                        acc[i][j] += a[i] * w[j];
            }
            __syncthreads();
        }
    }
    #pragma unroll
    for (int j = 0; j < 4; j++) {
        int n = n0 + tx * 4 + j;
        float bj = b1[n];
        if (DUAL) bj += b2[n];
        #pragma unroll
        for (int i = 0; i < 4; i++) {
            int m = m0 + ty * 4 + i;
            C[(size_t)m * 512 + n] = tanhf(acc[i][j] + bj);
        }
    }
}

// ---------------- K4: sentinel scores + gate ----------------
__global__ void sentinel_kernel(const void* __restrict__ epoch_p,
                                const float* __restrict__ sT,
                                const float* __restrict__ rT,
                                const float* __restrict__ qh0,
                                const float* __restrict__ W_Ss, const float* __restrict__ b_Ss,
                                const float* __restrict__ W_Sr, const float* __restrict__ b_Sr,
                                const float* __restrict__ W_bq, const float* __restrict__ b_bq,
                                float* __restrict__ gama)
{
    int s = blockIdx.x;
    int lane = threadIdx.x;
    int iv = *(const int*)epoch_p;
    int epoch = (iv >= 0 && iv < 1000000) ? iv : (int)(*(const float*)epoch_p);
    if (epoch <= 20) { if (lane == 0) gama[s] = 1.0f; return; }

    const float* srow = sT + (size_t)s * EE;
    const float* rrow = rT + (size_t)s * EE;
    float ss = 0.f, sr = 0.f;
    #pragma unroll
    for (int j = 0; j < NT; j++) {
        const float* w1 = W_Ss + (size_t)j * EE;
        const float* w2 = W_Sr + (size_t)j * EE;
        float p1 = 0.f, p2 = 0.f;
        for (int i = lane; i < EE; i += 32) { p1 += srow[i] * w1[i]; p2 += rrow[i] * w2[i]; }
        #pragma unroll
        for (int o = 16; o; o >>= 1) {
            p1 += __shfl_xor_sync(0xffffffffu, p1, o);
            p2 += __shfl_xor_sync(0xffffffffu, p2, o);
        }
        float qh = qh0[(size_t)s * NT + j];
        ss += tanhf(p1 + b_Ss[j] + qh) * W_bq[j];
        sr += tanhf(p2 + b_Sr[j] + qh) * W_bq[j];
    }
    if (lane == 0) {
        float d = ss - sr;
        gama[s] = 1.0f / (1.0f + expf(-d));
    }
}

// ---------------- K5: c_t mix ----------------
__global__ void mix_kernel(const float* __restrict__ sT, const float* __restrict__ rT,
                           const float* __restrict__ gama, float* __restrict__ c)
{
    int idx = blockIdx.x * blockDim.x + threadIdx.x;
    if (idx >= ROWS * EE) return;
    int srow = (idx >> 9) & 127;
    float g = gama[srow];
    c[idx] = g * sT[idx] + (1.0f - g) * rT[idx];
}

// ---------------- K6: vocab GEMM via TF32 mma.sync ----------------
// M=2048, N=30000, K=512; BM=BN=128, BK=16, 256 threads (2x4 warps, 64x32 warp tile)
#define SA 20   // padded SMEM row stride (floats): conflict-free ldmatrix

__device__ __forceinline__ unsigned f2tf32(float x) {
    unsigned r;
    asm("cvt.rna.tf32.f32 %0, %1;" : "=r"(r) : "f"(x));
    return r;
}

__device__ __forceinline__ void ldsm_x4(unsigned& r0, unsigned& r1, unsigned& r2, unsigned& r3,
                                        unsigned addr) {
    asm volatile("ldmatrix.sync.aligned.m8n8.x4.shared.b16 {%0,%1,%2,%3}, [%4];"
                 : "=r"(r0), "=r"(r1), "=r"(r2), "=r"(r3) : "r"(addr));
}

__device__ __forceinline__ void mma_tf32(float* d, const unsigned* a, unsigned b0, unsigned b1) {
    asm volatile(
        "mma.sync.aligned.m16n8k8.row.col.f32.tf32.tf32.f32 "
        "{%0,%1,%2,%3}, {%4,%5,%6,%7}, {%8,%9}, {%0,%1,%2,%3};"
        : "+f"(d[0]), "+f"(d[1]), "+f"(d[2]), "+f"(d[3])
        : "r"(a[0]), "r"(a[1]), "r"(a[2]), "r"(a[3]), "r"(b0), "r"(b1));
}

__global__ __launch_bounds__(256, 2)
void vocab_gemm_tf32(const float* __restrict__ A,      // [2048,512]
                     const float* __restrict__ W,      // [30000,512]
                     const float* __restrict__ bias,   // [30000]
                     float* __restrict__ C)            // [2048,30000]
{
    __shared__ unsigned As[2][128 * SA];
    __shared__ unsigned Ws[2][128 * SA];

    int tid = threadIdx.x;
    int warp = tid >> 5, lane = tid & 31;
    int wm = warp >> 2, wn = warp & 3;              // 2 x 4 warp grid
    int m0 = blockIdx.x * 128;                      // m-fast for L2 W reuse
    int n0 = blockIdx.y * 128;

    // global loader: thread -> (row lm, k-offset lf), 8 consecutive k each
    int lm = tid >> 1;
    int lf = (tid & 1) * 8;
    const float* Ag = A + (size_t)(m0 + lm) * 512 + lf;
    bool wok = (n0 + lm) < VOCAB;
    const float* Wg = W + (size_t)(n0 + lm) * 512 + lf;

    // ldmatrix per-thread source row/word (8x8 b16 matrix = 8 rows x 4 words)
    int grp = lane >> 3;
    int lrow = (lane & 7) + (grp & 1) * 8;
    int lword = (grp >> 1) * 4;

    float acc[4][4][4] = {};                        // [mt][nt][reg]
    float4 pa0, pa1, pw0, pw1;

    // fetch tile kt into registers
    auto fetch = [&](int k0) {
        pa0 = *(const float4*)(Ag + k0);
        pa1 = *(const float4*)(Ag + k0 + 4);
        if (wok) {
            pw0 = *(const float4*)(Wg + k0);
            pw1 = *(const float4*)(Wg + k0 + 4);
        } else {
            pw0 = make_float4(0.f, 0.f, 0.f, 0.f);
            pw1 = pw0;
        }
    };
    // store registers (cvt to tf32) into smem buffer
    auto storetile = [&](int buf) {
        unsigned* ap = &As[buf][lm * SA + lf];
        ap[0] = f2tf32(pa0.x); ap[1] = f2tf32(pa0.y); ap[2] = f2tf32(pa0.z); ap[3] = f2tf32(pa0.w);
        ap[4] = f2tf32(pa1.x); ap[5] = f2tf32(pa1.y); ap[6] = f2tf32(pa1.z); ap[7] = f2tf32(pa1.w);
        unsigned* wp = &Ws[buf][lm * SA + lf];
        wp[0] = f2tf32(pw0.x); wp[1] = f2tf32(pw0.y); wp[2] = f2tf32(pw0.z); wp[3] = f2tf32(pw0.w);
        wp[4] = f2tf32(pw1.x); wp[5] = f2tf32(pw1.y); wp[6] = f2tf32(pw1.z); wp[7] = f2tf32(pw1.w);
    };

    fetch(0);
    storetile(0);
    __syncthreads();

    for (int kt = 0; kt < 32; kt++) {
        int buf = kt & 1;
        if (kt < 31) fetch((kt + 1) * 16);

        #pragma unroll
        for (int ks = 0; ks < 2; ks++) {
            unsigned af[4][4];
            #pragma unroll
            for (int mt = 0; mt < 4; mt++) {
                int row = wm * 64 + mt * 16 + lrow;
                unsigned addr = (unsigned)__cvta_generic_to_shared(
                    &As[buf][row * SA + ks * 8 + lword]);
                ldsm_x4(af[mt][0], af[mt][1], af[mt][2], af[mt][3], addr);
            }
            unsigned bf[2][4];
            #pragma unroll
            for (int np = 0; np < 2; np++) {
                int row = wn * 32 + np * 16 + lrow;
                unsigned addr = (unsigned)__cvta_generic_to_shared(
                    &Ws[buf][row * SA + ks * 8 + lword]);
                ldsm_x4(bf[np][0], bf[np][1], bf[np][2], bf[np][3], addr);
            }
            #pragma unroll
            for (int mt = 0; mt < 4; mt++)
                #pragma unroll
                for (int nt = 0; nt < 4; nt++) {
                    unsigned b0 = bf[nt >> 1][nt & 1];
                    unsigned b1 = bf[nt >> 1][(nt & 1) + 2];
                    mma_tf32(acc[mt][nt], af[mt], b0, b1);
                }
        }

        if (kt < 31) {
            __syncthreads();
            storetile(buf ^ 1);
            __syncthreads();
        }
    }

    // epilogue: c0:(r, c), c1:(r, c+1), c2:(r+8, c), c3:(r+8, c+1)
    int r = lane >> 2;
    int cb = 2 * (lane & 3);
    #pragma unroll
    for (int nt = 0; nt < 4; nt++) {
        int cn = n0 + wn * 32 + nt * 8 + cb;
        if (cn < VOCAB) {
            float b0 = __ldg(bias + cn), b1 = __ldg(bias + cn + 1);
            #pragma unroll
            for (int mt = 0; mt < 4; mt++) {
                int rm = m0 + wm * 64 + mt * 16 + r;
                float2 v0 = make_float2(acc[mt][nt][0] + b0, acc[mt][nt][1] + b1);
                float2 v1 = make_float2(acc[mt][nt][2] + b0, acc[mt][nt][3] + b1);
                *(float2*)(C + (size_t)rm * VOCAB + cn) = v0;
                *(float2*)(C + (size_t)(rm + 8) * VOCAB + cn) = v1;
            }
        }
    }
}

// ---------------- launch ----------------
extern "C" void kernel_launch(void* const* d_in, const int* in_sizes, int n_in,
                              void* d_out, int out_size)
{
    const void*  epoch = d_in[0];
    const float* h_t  = (const float*)d_in[1];
    const float* V    = (const float*)d_in[2];
    const float* T    = (const float*)d_in[3];
    const float* W_ZV = (const float*)d_in[4];   const float* b_ZV = (const float*)d_in[5];
    const float* W_Zh = (const float*)d_in[6];   const float* b_Zh = (const float*)d_in[7];
    const float* W_az = (const float*)d_in[8];   const float* b_az = (const float*)d_in[9];
    const float* W_QT = (const float*)d_in[10];  const float* b_QT = (const float*)d_in[11];
    const float* W_Qh = (const float*)d_in[12];  const float* b_Qh = (const float*)d_in[13];
    const float* W_bq = (const float*)d_in[14];  const float* b_bq = (const float*)d_in[15];
    const float* W_sq = (const float*)d_in[16];  const float* b_sq = (const float*)d_in[17];
    const float* W_sh = (const float*)d_in[18];  const float* b_sh = (const float*)d_in[19];
    const float* W_Ss = (const float*)d_in[20];  const float* b_Ss = (const float*)d_in[21];
    const float* W_Sr = (const float*)d_in[22];  const float* b_Sr = (const float*)d_in[23];
    const float* W_sz = (const float*)d_in[24];  const float* b_sz = (const float*)d_in[25];
    const float* W_mlp= (const float*)d_in[26];  const float* b_mlp= (const float*)d_in[27];
    float* out = (float*)d_out;

    float *linV, *linH, *linQT, *linQh, *z, *q, *r, *s, *c, *gama;
    cudaGetSymbolAddress((void**)&linV,  g_linV);
    cudaGetSymbolAddress((void**)&linH,  g_linH);
    cudaGetSymbolAddress((void**)&linQT, g_linQT);
    cudaGetSymbolAddress((void**)&linQh, g_linQh);
    cudaGetSymbolAddress((void**)&z,     g_z);
    cudaGetSymbolAddress((void**)&q,     g_q);
    cudaGetSymbolAddress((void**)&r,     g_r);
    cudaGetSymbolAddress((void**)&s,     g_s);
    cudaGetSymbolAddress((void**)&c,     g_c);
    cudaGetSymbolAddress((void**)&gama,  g_gama);

    // K0: small linears
    small_lin_kernel<<<BB*KK, 128>>>(V,   W_ZV, b_ZV, linV,  KK);
    small_lin_kernel<<<ROWS,  128>>>(h_t, W_Zh, b_Zh, linH,  KK);
    small_lin_kernel<<<BB*NT, 128>>>(T,   W_QT, b_QT, linQT, NT);
    small_lin_kernel<<<ROWS,  128>>>(h_t, W_Qh, b_Qh, linQh, NT);

    // K1/K2: attentions
    visual_kernel<<<ROWS, 256>>>(V, linV, linH, W_az, b_az, z);
    topic_kernel <<<ROWS, 256>>>(T, linQT, linQh, W_bq, b_bq, q);

    // K3: mid GEMMs
    mid_gemm_tanh<true ><<<dim3(512/64, ROWS/64), 256>>>(q, W_sq, b_sq, h_t, W_sh, b_sh, s);
    mid_gemm_tanh<false><<<dim3(512/64, ROWS/64), 256>>>(z, W_sz, b_sz, nullptr, nullptr, nullptr, r);

    // K4: sentinel gate
    sentinel_kernel<<<SS, 32>>>(epoch, s, r, linQh, W_Ss, b_Ss, W_Sr, b_Sr, W_bq, b_bq, gama);

    // K5: mix
    mix_kernel<<<(ROWS*EE + 255)/256, 256>>>(s, r, gama, c);

    // K6: vocab projection (TF32 tensor core); grid m-fast so W tiles reused in L2
    vocab_gemm_tf32<<<dim3(ROWS/128, (VOCAB + 127)/128), 256>>>(c, W_mlp, b_mlp, out);
}